// round 3
// baseline (speedup 1.0000x reference)
#include <cuda_runtime.h>
#include <stdint.h>

#define NMAX 200000
#define EMAX 400000
#define GMAX 8192
#define HMAX 256
#define BN_EPS 1e-5f

// ---------------- scratch (device globals: no allocation allowed) ----------
__device__ float g_dis[NMAX];                       // deg -> rsqrt(deg)
__device__ float g_hw[(size_t)NMAX * HMAX];         // x@W result
__device__ float g_agg[(size_t)NMAX * HMAX];        // aggregated
__device__ float g_colsum[HMAX];
__device__ float g_colsumsq[HMAX];
__device__ float g_scale[HMAX];
__device__ float g_shift[HMAX];
__device__ float g_pooled[(size_t)GMAX * HMAX];
__device__ float g_cnt[GMAX];
__device__ float g_pm[(size_t)GMAX * HMAX];

// ---------------- small utility kernels ------------------------------------
__global__ void k_fill(float* p, long n, float v) {
    long i = (long)blockIdx.x * blockDim.x + threadIdx.x;
    if (i < n) p[i] = v;
}

__global__ void k_deg_count(const int* __restrict__ dst, float* __restrict__ deg, int E) {
    int e = blockIdx.x * blockDim.x + threadIdx.x;
    if (e < E) atomicAdd(&deg[dst[e]], 1.0f);
}

__global__ void k_rsqrt_inplace(float* p, int n) {
    int i = blockIdx.x * blockDim.x + threadIdx.x;
    if (i < n) p[i] = rsqrtf(p[i]);
}

// ---------------- layer-1 GEMM: [N,9] @ [9,128] -----------------------------
__global__ void k_gemm1(const float* __restrict__ x, const float* __restrict__ W,
                        float* __restrict__ out, int N) {
    __shared__ float Ws[9 * 128];
    __shared__ float xs[8 * 9];
    int tid = threadIdx.x;
    for (int i = tid; i < 9 * 128; i += 256) Ws[i] = W[i];
    int r0 = blockIdx.x * 8;
    if (tid < 72) {
        int rr = tid / 9, cc = tid % 9;
        int r = r0 + rr;
        xs[tid] = (r < N) ? x[(size_t)r * 9 + cc] : 0.0f;
    }
    __syncthreads();
    int lr = tid >> 5;            // 0..7  (row within block)
    int c4 = (tid & 31) * 4;      // 0..124
    int r = r0 + lr;
    if (r >= N) return;
    float a0 = 0.f, a1 = 0.f, a2 = 0.f, a3 = 0.f;
#pragma unroll
    for (int k = 0; k < 9; k++) {
        float xv = xs[lr * 9 + k];
        const float* w = &Ws[k * 128 + c4];
        a0 += xv * w[0]; a1 += xv * w[1]; a2 += xv * w[2]; a3 += xv * w[3];
    }
    float4 v = make_float4(a0, a1, a2, a3);
    *(float4*)&out[(size_t)r * 128 + c4] = v;
}

// ---------------- self-loop init: agg = dis[i]^2 * hw[i] --------------------
__global__ void k_selfloop(const float* __restrict__ hw, const float* __restrict__ dis,
                           float* __restrict__ agg, int N, int H, int lq) {
    long total = (long)N << lq;
    long stride = (long)gridDim.x * blockDim.x;
    for (long idx = (long)blockIdx.x * blockDim.x + threadIdx.x; idx < total; idx += stride) {
        int i = (int)(idx >> lq);
        int j = (int)(idx & ((1 << lq) - 1)) * 4;
        float d = dis[i];
        float w = d * d;
        float4 v = *(const float4*)&hw[(size_t)i * H + j];
        v.x *= w; v.y *= w; v.z *= w; v.w *= w;
        *(float4*)&agg[(size_t)i * H + j] = v;
    }
}

// ---------------- edge scatter: agg[dst] += dis[s]*dis[d] * hw[src] ---------
__global__ void k_edge_agg(const int* __restrict__ src, const int* __restrict__ dst,
                           const float* __restrict__ dis, const float* __restrict__ hw,
                           float* __restrict__ agg, int E, int H, int lq) {
    long total = (long)E << lq;
    long stride = (long)gridDim.x * blockDim.x;
    for (long idx = (long)blockIdx.x * blockDim.x + threadIdx.x; idx < total; idx += stride) {
        long e = idx >> lq;
        int j = (int)(idx & ((1 << lq) - 1)) * 4;
        int s = src[e];
        int d = dst[e];
        float w = dis[s] * dis[d];
        float4 v = *(const float4*)&hw[(size_t)s * H + j];
        float* p = &agg[(size_t)d * H + j];
        atomicAdd(p + 0, v.x * w);
        atomicAdd(p + 1, v.y * w);
        atomicAdd(p + 2, v.z * w);
        atomicAdd(p + 3, v.w * w);
    }
}

// ---------------- BN stats (one-pass sum & sumsq per column) ----------------
__global__ void k_stats(const float* __restrict__ agg, int N, int H) {
    int c = threadIdx.x;   // blockDim.x == H
    float s = 0.f, ss = 0.f;
    for (int r = blockIdx.x; r < N; r += gridDim.x) {
        float v = agg[(size_t)r * H + c];
        s += v; ss += v * v;
    }
    atomicAdd(&g_colsum[c], s);
    atomicAdd(&g_colsumsq[c], ss);
}

__global__ void k_zero_stats(int H) {
    int c = threadIdx.x;
    if (c < H) { g_colsum[c] = 0.f; g_colsumsq[c] = 0.f; }
}

__global__ void k_finalize_bn(const float* __restrict__ gam, const float* __restrict__ bet,
                              int N, int H) {
    int c = threadIdx.x;
    if (c >= H) return;
    float inv = 1.0f / (float)N;
    float mean = g_colsum[c] * inv;
    float var = fmaxf(g_colsumsq[c] * inv - mean * mean, 0.f);
    float sc = gam[c] * rsqrtf(var + BN_EPS);
    g_scale[c] = sc;
    g_shift[c] = bet[c] - mean * sc;
}

// ---------------- generic SGEMM: C = op(A[M,K]) @ W[K,Nc] (+bias) -----------
// op = relu(a * scale[k] + shift[k]) when BN==true (fused BN+ReLU on input)
template <bool BN, bool BIAS>
__global__ void __launch_bounds__(256)
k_sgemm(const float* __restrict__ A, const float* __restrict__ W,
        float* __restrict__ C, int M, int K, int Nc,
        const float* __restrict__ scale, const float* __restrict__ shift,
        const float* __restrict__ bias) {
    __shared__ float As[16][132];   // padded, keeps float4 alignment
    __shared__ float Ws[16][128];

    int tid = threadIdx.x;
    int tx = tid & 15;     // 0..15 -> 8 output cols each
    int ty = tid >> 4;     // 0..15 -> 8 output rows each
    int rowBase = blockIdx.y * 128;
    int colBase = blockIdx.x * 128;

    float acc[8][8];
#pragma unroll
    for (int i = 0; i < 8; i++)
#pragma unroll
        for (int j = 0; j < 8; j++) acc[i][j] = 0.f;

    for (int k0 = 0; k0 < K; k0 += 16) {
        // load A tile: 128x16 floats (512 float4, 2 per thread), BN+relu fused
#pragma unroll
        for (int l = 0; l < 2; l++) {
            int lin = tid + l * 256;
            int ar = lin >> 2;          // 0..127
            int ac = (lin & 3) * 4;     // 0,4,8,12
            int r = rowBase + ar;
            float4 v = make_float4(0.f, 0.f, 0.f, 0.f);
            if (r < M) v = *(const float4*)&A[(size_t)r * K + k0 + ac];
            if (BN) {
                v.x = fmaxf(v.x * scale[k0 + ac + 0] + shift[k0 + ac + 0], 0.f);
                v.y = fmaxf(v.y * scale[k0 + ac + 1] + shift[k0 + ac + 1], 0.f);
                v.z = fmaxf(v.z * scale[k0 + ac + 2] + shift[k0 + ac + 2], 0.f);
                v.w = fmaxf(v.w * scale[k0 + ac + 3] + shift[k0 + ac + 3], 0.f);
            }
            As[ac + 0][ar] = v.x; As[ac + 1][ar] = v.y;
            As[ac + 2][ar] = v.z; As[ac + 3][ar] = v.w;
        }
        // load W tile: 16x128 floats
#pragma unroll
        for (int l = 0; l < 2; l++) {
            int lin = tid + l * 256;
            int wr = lin >> 5;          // 0..15
            int wc = (lin & 31) * 4;    // 0..124
            *(float4*)&Ws[wr][wc] = *(const float4*)&W[(size_t)(k0 + wr) * Nc + colBase + wc];
        }
        __syncthreads();
#pragma unroll
        for (int k = 0; k < 16; k++) {
            float4 a0 = *(float4*)&As[k][ty * 8];
            float4 a1 = *(float4*)&As[k][ty * 8 + 4];
            float4 b0 = *(float4*)&Ws[k][tx * 8];
            float4 b1 = *(float4*)&Ws[k][tx * 8 + 4];
            float ar[8] = {a0.x, a0.y, a0.z, a0.w, a1.x, a1.y, a1.z, a1.w};
            float br[8] = {b0.x, b0.y, b0.z, b0.w, b1.x, b1.y, b1.z, b1.w};
#pragma unroll
            for (int i = 0; i < 8; i++)
#pragma unroll
                for (int j = 0; j < 8; j++) acc[i][j] += ar[i] * br[j];
        }
        __syncthreads();
    }

#pragma unroll
    for (int i = 0; i < 8; i++) {
        int r = rowBase + ty * 8 + i;
        if (r >= M) continue;
#pragma unroll
        for (int j = 0; j < 8; j += 4) {
            int c = colBase + tx * 8 + j;
            float4 v = make_float4(acc[i][j], acc[i][j + 1], acc[i][j + 2], acc[i][j + 3]);
            if (BIAS) { v.x += bias[c]; v.y += bias[c + 1]; v.z += bias[c + 2]; v.w += bias[c + 3]; }
            *(float4*)&C[(size_t)r * Nc + c] = v;
        }
    }
}

// ---------------- pooling --------------------------------------------------
__global__ void k_pool_count(const int* __restrict__ batch, int N) {
    int i = blockIdx.x * blockDim.x + threadIdx.x;
    if (i < N) atomicAdd(&g_cnt[batch[i]], 1.0f);
}

__global__ void k_pool_add(const float* __restrict__ agg, const int* __restrict__ batch,
                           int N) {
    long total = (long)N * 64;   // H=256 -> 64 float4 per row
    long stride = (long)gridDim.x * blockDim.x;
    for (long idx = (long)blockIdx.x * blockDim.x + threadIdx.x; idx < total; idx += stride) {
        int i = (int)(idx >> 6);
        int j = (int)(idx & 63) * 4;
        float4 v = *(const float4*)&agg[(size_t)i * 256 + j];
        v.x = fmaxf(v.x * g_scale[j + 0] + g_shift[j + 0], 0.f);
        v.y = fmaxf(v.y * g_scale[j + 1] + g_shift[j + 1], 0.f);
        v.z = fmaxf(v.z * g_scale[j + 2] + g_shift[j + 2], 0.f);
        v.w = fmaxf(v.w * g_scale[j + 3] + g_shift[j + 3], 0.f);
        int b = batch[i];
        float* p = &g_pooled[(size_t)b * 256 + j];
        atomicAdd(p + 0, v.x);
        atomicAdd(p + 1, v.y);
        atomicAdd(p + 2, v.z);
        atomicAdd(p + 3, v.w);
    }
}

__global__ void k_pool_div(int G) {
    long total = (long)G * 256;
    long i = (long)blockIdx.x * blockDim.x + threadIdx.x;
    if (i < total) {
        int g = (int)(i >> 8);
        g_pm[i] = g_pooled[i] / fmaxf(g_cnt[g], 1.0f);
    }
}

// ---------------- host driver ----------------------------------------------
extern "C" void kernel_launch(void* const* d_in, const int* in_sizes, int n_in,
                              void* d_out, int out_size) {
    const float* x = (const float*)d_in[0];
    const int* ei = (const int*)d_in[1];      // int32 (JAX x64 disabled)
    const int* batch = (const int*)d_in[2];   // int32
    // num_graphs scalar may or may not be a device input -> detect by size
    int o = (in_sizes[3] == 1) ? 4 : 3;
    const float* W1 = (const float*)d_in[o + 0];
    const float* gm1 = (const float*)d_in[o + 2];
    const float* be1 = (const float*)d_in[o + 3];
    const float* W2 = (const float*)d_in[o + 4];
    const float* gm2 = (const float*)d_in[o + 6];
    const float* be2 = (const float*)d_in[o + 7];
    const float* W3 = (const float*)d_in[o + 8];
    const float* gm3 = (const float*)d_in[o + 10];
    const float* be3 = (const float*)d_in[o + 11];
    const float* Wp = (const float*)d_in[o + 12];
    const float* bp = (const float*)d_in[o + 13];

    int N = in_sizes[0] / 9;
    int E = in_sizes[1] / 2;
    int P = in_sizes[o + 13];
    int G = out_size / P;

    float *dis, *hw, *agg, *pooled, *cnt, *pm, *scale, *shift;
    cudaGetSymbolAddress((void**)&dis, g_dis);
    cudaGetSymbolAddress((void**)&hw, g_hw);
    cudaGetSymbolAddress((void**)&agg, g_agg);
    cudaGetSymbolAddress((void**)&pooled, g_pooled);
    cudaGetSymbolAddress((void**)&cnt, g_cnt);
    cudaGetSymbolAddress((void**)&pm, g_pm);
    cudaGetSymbolAddress((void**)&scale, g_scale);
    cudaGetSymbolAddress((void**)&shift, g_shift);

    const int* src = ei;
    const int* dst = ei + E;

    // degree / norm
    k_fill<<<(N + 255) / 256, 256>>>(dis, N, 1.0f);       // self-loop contributes 1
    k_deg_count<<<(E + 255) / 256, 256>>>(dst, dis, E);
    k_rsqrt_inplace<<<(N + 255) / 256, 256>>>(dis, N);

    // ---- layer 1: x@W1 -> aggregate -> BN params (bias cancels in BN) ----
    k_gemm1<<<(N + 7) / 8, 256>>>(x, W1, hw, N);
    k_selfloop<<<8192, 256>>>(hw, dis, agg, N, 128, 5);
    k_edge_agg<<<16384, 256>>>(src, dst, dis, hw, agg, E, 128, 5);
    k_zero_stats<<<1, 128>>>(128);
    k_stats<<<1024, 128>>>(agg, N, 128);
    k_finalize_bn<<<1, 128>>>(gm1, be1, N, 128);

    // ---- layer 2: relu(BN(agg)) @ W2 -> aggregate -> BN params ----
    {
        dim3 grid(256 / 128, (N + 127) / 128);
        k_sgemm<true, false><<<grid, 256>>>(agg, W2, hw, N, 128, 256, scale, shift, nullptr);
    }
    k_selfloop<<<8192, 256>>>(hw, dis, agg, N, 256, 6);
    k_edge_agg<<<16384, 256>>>(src, dst, dis, hw, agg, E, 256, 6);
    k_zero_stats<<<1, 256>>>(256);
    k_stats<<<1024, 256>>>(agg, N, 256);
    k_finalize_bn<<<1, 256>>>(gm2, be2, N, 256);

    // ---- layer 3 ----
    {
        dim3 grid(256 / 128, (N + 127) / 128);
        k_sgemm<true, false><<<grid, 256>>>(agg, W3, hw, N, 256, 256, scale, shift, nullptr);
    }
    k_selfloop<<<8192, 256>>>(hw, dis, agg, N, 256, 6);
    k_edge_agg<<<16384, 256>>>(src, dst, dis, hw, agg, E, 256, 6);
    k_zero_stats<<<1, 256>>>(256);
    k_stats<<<1024, 256>>>(agg, N, 256);
    k_finalize_bn<<<1, 256>>>(gm3, be3, N, 256);

    // ---- pooling (BN3 + relu fused) ----
    k_fill<<<((long)G * 256 + 255) / 256, 256>>>(pooled, (long)G * 256, 0.0f);
    k_fill<<<(G + 255) / 256, 256>>>(cnt, G, 0.0f);
    k_pool_count<<<(N + 255) / 256, 256>>>(batch, N);
    k_pool_add<<<16384, 256>>>(agg, batch, N);
    k_pool_div<<<((long)G * 256 + 255) / 256, 256>>>(G);

    // ---- head: pm @ Wp + bp -> d_out ----
    {
        dim3 grid(P / 128, (G + 127) / 128);
        k_sgemm<false, true><<<grid, 256>>>(pm, Wp, (float*)d_out, G, 256, P,
                                            nullptr, nullptr, bp);
    }
}

// round 4
// speedup vs baseline: 1.3969x; 1.3969x over previous
#include <cuda_runtime.h>
#include <stdint.h>

#define NMAX 200000
#define EMAX 400000
#define GMAX 8192
#define HMAX 256
#define BN_EPS 1e-5f

// ---------------- scratch (device globals: no allocation allowed) ----------
__device__ float g_dis[NMAX];
__device__ float g_hw[(size_t)NMAX * HMAX];
__device__ float g_agg[(size_t)NMAX * HMAX];
__device__ float g_colsum[HMAX];
__device__ float g_colsumsq[HMAX];
__device__ float g_scale[HMAX];
__device__ float g_shift[HMAX];
__device__ float g_pm[(size_t)GMAX * HMAX];
// CSR / pooling structures
__device__ int g_rowcnt[NMAX];
__device__ int g_rowptr[NMAX + 1];
__device__ int g_fill[NMAX];
__device__ int g_esrc[EMAX];
__device__ int g_gcnt[GMAX];
__device__ int g_gptr[GMAX + 1];
__device__ int g_bsum[1024];
__device__ int g_boff[1024];
__device__ int g_dummy[4];

// ---------------- small utility kernels ------------------------------------
__global__ void k_zero_int(int* p, int n) {
    int i = blockIdx.x * blockDim.x + threadIdx.x;
    if (i < n) p[i] = 0;
}

__global__ void k_set_int(int* p, int v) { *p = v; }

__global__ void k_count(const int* __restrict__ idx, int* __restrict__ cnt, int n) {
    int i = blockIdx.x * blockDim.x + threadIdx.x;
    if (i < n) atomicAdd(&cnt[idx[i]], 1);
}

__global__ void k_dis(const int* __restrict__ cnt, float* __restrict__ dis, int n) {
    int i = blockIdx.x * blockDim.x + threadIdx.x;
    if (i < n) dis[i] = rsqrtf((float)cnt[i] + 1.0f);   // +1 = self loop
}

// ---------------- 2-level exclusive scan (chunk = 1024) ---------------------
__global__ void k_scan1(const int* __restrict__ in, int n, int* __restrict__ out,
                        int* __restrict__ bsum) {
    __shared__ int sh[256];
    int t = threadIdx.x;
    int base = blockIdx.x * 1024 + t * 4;
    int v0 = (base + 0 < n) ? in[base + 0] : 0;
    int v1 = (base + 1 < n) ? in[base + 1] : 0;
    int v2 = (base + 2 < n) ? in[base + 2] : 0;
    int v3 = (base + 3 < n) ? in[base + 3] : 0;
    int s = v0 + v1 + v2 + v3;
    sh[t] = s;
    __syncthreads();
    for (int off = 1; off < 256; off <<= 1) {
        int x = (t >= off) ? sh[t - off] : 0;
        __syncthreads();
        sh[t] += x;
        __syncthreads();
    }
    int run = sh[t] - s;   // exclusive prefix of this thread
    if (base + 0 < n) out[base + 0] = run; run += v0;
    if (base + 1 < n) out[base + 1] = run; run += v1;
    if (base + 2 < n) out[base + 2] = run; run += v2;
    if (base + 3 < n) out[base + 3] = run;
    if (t == 0) bsum[blockIdx.x] = sh[255];
}

__global__ void k_scan_add(int* __restrict__ out, const int* __restrict__ boff, int n) {
    int i = blockIdx.x * blockDim.x + threadIdx.x;
    if (i < n) out[i] += boff[i >> 10];
}

// ---------------- CSR fill ---------------------------------------------------
__global__ void k_csr_fill(const int* __restrict__ src, const int* __restrict__ dst,
                           const int* __restrict__ rowptr, int* __restrict__ fill,
                           int* __restrict__ esrc, int E) {
    int e = blockIdx.x * blockDim.x + threadIdx.x;
    if (e < E) {
        int d = dst[e];
        int pos = rowptr[d] + atomicAdd(&fill[d], 1);
        esrc[pos] = src[e];
    }
}

// ---------------- layer-1 GEMM: [N,9] @ [9,128] -----------------------------
__global__ void k_gemm1(const float* __restrict__ x, const float* __restrict__ W,
                        float* __restrict__ out, int N) {
    __shared__ float Ws[9 * 128];
    __shared__ float xs[8 * 9];
    int tid = threadIdx.x;
    for (int i = tid; i < 9 * 128; i += 256) Ws[i] = W[i];
    int r0 = blockIdx.x * 8;
    if (tid < 72) {
        int rr = tid / 9, cc = tid % 9;
        int r = r0 + rr;
        xs[tid] = (r < N) ? x[(size_t)r * 9 + cc] : 0.0f;
    }
    __syncthreads();
    int lr = tid >> 5;
    int c4 = (tid & 31) * 4;
    int r = r0 + lr;
    if (r >= N) return;
    float a0 = 0.f, a1 = 0.f, a2 = 0.f, a3 = 0.f;
#pragma unroll
    for (int k = 0; k < 9; k++) {
        float xv = xs[lr * 9 + k];
        const float* w = &Ws[k * 128 + c4];
        a0 += xv * w[0]; a1 += xv * w[1]; a2 += xv * w[2]; a3 += xv * w[3];
    }
    *(float4*)&out[(size_t)r * 128 + c4] = make_float4(a0, a1, a2, a3);
}

// ---------------- CSR gather: agg[d] = dis[d]*(sum_e dis[s]*hw[s] + dis[d]*hw[d])
template <int H>
__global__ void k_gather(const float* __restrict__ hw, const float* __restrict__ dis,
                         const int* __restrict__ rowptr, const int* __restrict__ esrc,
                         float* __restrict__ agg, int N) {
    int warp = (blockIdx.x * blockDim.x + threadIdx.x) >> 5;
    int lane = threadIdx.x & 31;
    if (warp >= N) return;
    int d = warp;
    constexpr int V = H / 128;            // float4 per lane
    int c = lane * (H / 32);
    float4 acc[V];
#pragma unroll
    for (int v = 0; v < V; v++) acc[v] = make_float4(0.f, 0.f, 0.f, 0.f);
    int e0 = rowptr[d], e1 = rowptr[d + 1];
    for (int e = e0; e < e1; e++) {
        int s = esrc[e];
        float w = dis[s];
        const float* row = &hw[(size_t)s * H + c];
#pragma unroll
        for (int v = 0; v < V; v++) {
            float4 x = *(const float4*)&row[v * 4];
            acc[v].x += w * x.x; acc[v].y += w * x.y;
            acc[v].z += w * x.z; acc[v].w += w * x.w;
        }
    }
    float dd = dis[d];
    const float* self = &hw[(size_t)d * H + c];
    float* outp = &agg[(size_t)d * H + c];
#pragma unroll
    for (int v = 0; v < V; v++) {
        float4 x = *(const float4*)&self[v * 4];
        float4 r;
        r.x = dd * (acc[v].x + dd * x.x);
        r.y = dd * (acc[v].y + dd * x.y);
        r.z = dd * (acc[v].z + dd * x.z);
        r.w = dd * (acc[v].w + dd * x.w);
        *(float4*)&outp[v * 4] = r;
    }
}

// ---------------- BN stats ---------------------------------------------------
__global__ void k_stats(const float* __restrict__ agg, int N, int H) {
    int c = threadIdx.x;
    float s = 0.f, ss = 0.f;
    for (int r = blockIdx.x; r < N; r += gridDim.x) {
        float v = agg[(size_t)r * H + c];
        s += v; ss += v * v;
    }
    atomicAdd(&g_colsum[c], s);
    atomicAdd(&g_colsumsq[c], ss);
}

__global__ void k_zero_stats(int H) {
    int c = threadIdx.x;
    if (c < H) { g_colsum[c] = 0.f; g_colsumsq[c] = 0.f; }
}

__global__ void k_finalize_bn(const float* __restrict__ gam, const float* __restrict__ bet,
                              int N, int H) {
    int c = threadIdx.x;
    if (c >= H) return;
    float inv = 1.0f / (float)N;
    float mean = g_colsum[c] * inv;
    float var = fmaxf(g_colsumsq[c] * inv - mean * mean, 0.f);
    float sc = gam[c] * rsqrtf(var + BN_EPS);
    g_scale[c] = sc;
    g_shift[c] = bet[c] - mean * sc;
}

// ---------------- SGEMM with packed f32x2 FMA --------------------------------
__device__ __forceinline__ unsigned long long dup_f32x2(float a) {
    unsigned long long r;
    unsigned int u = __float_as_uint(a);
    asm("mov.b64 %0, {%1, %1};" : "=l"(r) : "r"(u));
    return r;
}
__device__ __forceinline__ void fma2(unsigned long long& acc, unsigned long long a,
                                     unsigned long long b) {
    asm("fma.rn.f32x2 %0, %1, %2, %0;" : "+l"(acc) : "l"(a), "l"(b));
}

union F4U2 { float4 f; unsigned long long u[2]; };

template <bool BN, bool BIAS>
__global__ void __launch_bounds__(256)
k_sgemm(const float* __restrict__ A, const float* __restrict__ W,
        float* __restrict__ C, int M, int K, int Nc,
        const float* __restrict__ scale, const float* __restrict__ shift,
        const float* __restrict__ bias) {
    __shared__ float As[16][132];
    __shared__ float Ws[16][128];

    int tid = threadIdx.x;
    int tx = tid & 15;
    int ty = tid >> 4;
    int rowBase = blockIdx.y * 128;
    int colBase = blockIdx.x * 128;

    unsigned long long acc2[8][4];
#pragma unroll
    for (int i = 0; i < 8; i++)
#pragma unroll
        for (int j = 0; j < 4; j++) acc2[i][j] = 0ULL;

    for (int k0 = 0; k0 < K; k0 += 16) {
#pragma unroll
        for (int l = 0; l < 2; l++) {
            int lin = tid + l * 256;
            int ar = lin >> 2;
            int ac = (lin & 3) * 4;
            int r = rowBase + ar;
            float4 v = make_float4(0.f, 0.f, 0.f, 0.f);
            if (r < M) v = *(const float4*)&A[(size_t)r * K + k0 + ac];
            if (BN) {
                v.x = fmaxf(v.x * scale[k0 + ac + 0] + shift[k0 + ac + 0], 0.f);
                v.y = fmaxf(v.y * scale[k0 + ac + 1] + shift[k0 + ac + 1], 0.f);
                v.z = fmaxf(v.z * scale[k0 + ac + 2] + shift[k0 + ac + 2], 0.f);
                v.w = fmaxf(v.w * scale[k0 + ac + 3] + shift[k0 + ac + 3], 0.f);
            }
            As[ac + 0][ar] = v.x; As[ac + 1][ar] = v.y;
            As[ac + 2][ar] = v.z; As[ac + 3][ar] = v.w;
        }
#pragma unroll
        for (int l = 0; l < 2; l++) {
            int lin = tid + l * 256;
            int wr = lin >> 5;
            int wc = (lin & 31) * 4;
            *(float4*)&Ws[wr][wc] = *(const float4*)&W[(size_t)(k0 + wr) * Nc + colBase + wc];
        }
        __syncthreads();
#pragma unroll
        for (int k = 0; k < 16; k++) {
            F4U2 a0, a1, b0, b1;
            a0.f = *(float4*)&As[k][ty * 8];
            a1.f = *(float4*)&As[k][ty * 8 + 4];
            b0.f = *(float4*)&Ws[k][tx * 8];
            b1.f = *(float4*)&Ws[k][tx * 8 + 4];
            float av[8] = {a0.f.x, a0.f.y, a0.f.z, a0.f.w, a1.f.x, a1.f.y, a1.f.z, a1.f.w};
            unsigned long long bp[4] = {b0.u[0], b0.u[1], b1.u[0], b1.u[1]};
#pragma unroll
            for (int i = 0; i < 8; i++) {
                unsigned long long ad = dup_f32x2(av[i]);
#pragma unroll
                for (int jp = 0; jp < 4; jp++) fma2(acc2[i][jp], ad, bp[jp]);
            }
        }
        __syncthreads();
    }

#pragma unroll
    for (int i = 0; i < 8; i++) {
        int r = rowBase + ty * 8 + i;
        if (r >= M) continue;
#pragma unroll
        for (int jp = 0; jp < 4; jp += 2) {
            int c = colBase + tx * 8 + jp * 2;
            unsigned long long u0 = acc2[i][jp], u1 = acc2[i][jp + 1];
            float4 v;
            v.x = __uint_as_float((unsigned)u0);
            v.y = __uint_as_float((unsigned)(u0 >> 32));
            v.z = __uint_as_float((unsigned)u1);
            v.w = __uint_as_float((unsigned)(u1 >> 32));
            if (BIAS) { v.x += bias[c]; v.y += bias[c + 1]; v.z += bias[c + 2]; v.w += bias[c + 3]; }
            *(float4*)&C[(size_t)r * Nc + c] = v;
        }
    }
}

// ---------------- segmented pooling (batch sorted) ---------------------------
__global__ void k_pool(const float* __restrict__ agg, const int* __restrict__ gptr,
                       float* __restrict__ pm) {
    int g = blockIdx.x;
    int c = threadIdx.x;      // 256
    int r0 = gptr[g], r1 = gptr[g + 1];
    float sc = g_scale[c], sh = g_shift[c];
    float s = 0.f;
    for (int r = r0; r < r1; r++) {
        float v = agg[(size_t)r * 256 + c];
        s += fmaxf(v * sc + sh, 0.f);
    }
    float cnt = (float)(r1 - r0);
    pm[(size_t)g * 256 + c] = s / fmaxf(cnt, 1.0f);
}

// ---------------- host driver ------------------------------------------------
static void exclusive_scan(int* data_in, int n, int* out, int* bsum, int* boff, int* dummy) {
    int nb = (n + 1023) / 1024;
    k_scan1<<<nb, 256>>>(data_in, n, out, bsum);
    k_scan1<<<1, 256>>>(bsum, nb, boff, dummy);
    k_scan_add<<<(n + 255) / 256, 256>>>(out, boff, n);
}

extern "C" void kernel_launch(void* const* d_in, const int* in_sizes, int n_in,
                              void* d_out, int out_size) {
    const float* x = (const float*)d_in[0];
    const int* ei = (const int*)d_in[1];
    const int* batch = (const int*)d_in[2];
    int o = (in_sizes[3] == 1) ? 4 : 3;
    const float* W1 = (const float*)d_in[o + 0];
    const float* gm1 = (const float*)d_in[o + 2];
    const float* be1 = (const float*)d_in[o + 3];
    const float* W2 = (const float*)d_in[o + 4];
    const float* gm2 = (const float*)d_in[o + 6];
    const float* be2 = (const float*)d_in[o + 7];
    const float* W3 = (const float*)d_in[o + 8];
    const float* gm3 = (const float*)d_in[o + 10];
    const float* be3 = (const float*)d_in[o + 11];
    const float* Wp = (const float*)d_in[o + 12];
    const float* bp = (const float*)d_in[o + 13];

    int N = in_sizes[0] / 9;
    int E = in_sizes[1] / 2;
    int P = in_sizes[o + 13];
    int G = out_size / P;

    float *dis, *hw, *agg, *pm, *scale, *shift;
    int *rowcnt, *rowptr, *fill, *esrc, *gcnt, *gptr, *bsum, *boff, *dummy;
    cudaGetSymbolAddress((void**)&dis, g_dis);
    cudaGetSymbolAddress((void**)&hw, g_hw);
    cudaGetSymbolAddress((void**)&agg, g_agg);
    cudaGetSymbolAddress((void**)&pm, g_pm);
    cudaGetSymbolAddress((void**)&scale, g_scale);
    cudaGetSymbolAddress((void**)&shift, g_shift);
    cudaGetSymbolAddress((void**)&rowcnt, g_rowcnt);
    cudaGetSymbolAddress((void**)&rowptr, g_rowptr);
    cudaGetSymbolAddress((void**)&fill, g_fill);
    cudaGetSymbolAddress((void**)&esrc, g_esrc);
    cudaGetSymbolAddress((void**)&gcnt, g_gcnt);
    cudaGetSymbolAddress((void**)&gptr, g_gptr);
    cudaGetSymbolAddress((void**)&bsum, g_bsum);
    cudaGetSymbolAddress((void**)&boff, g_boff);
    cudaGetSymbolAddress((void**)&dummy, g_dummy);

    const int* src = ei;
    const int* dst = ei + E;

    // ---- CSR build + norm ----
    k_zero_int<<<(N + 255) / 256, 256>>>(rowcnt, N);
    k_count<<<(E + 255) / 256, 256>>>(dst, rowcnt, E);
    k_dis<<<(N + 255) / 256, 256>>>(rowcnt, dis, N);
    exclusive_scan(rowcnt, N, rowptr, bsum, boff, dummy);
    k_set_int<<<1, 1>>>(rowptr + N, E);
    k_zero_int<<<(N + 255) / 256, 256>>>(fill, N);
    k_csr_fill<<<(E + 255) / 256, 256>>>(src, dst, rowptr, fill, esrc, E);

    // ---- graph segment ptrs (batch is sorted) ----
    k_zero_int<<<(G + 255) / 256, 256>>>(gcnt, G);
    k_count<<<(N + 255) / 256, 256>>>(batch, gcnt, N);
    exclusive_scan(gcnt, G, gptr, bsum, boff, dummy);
    k_set_int<<<1, 1>>>(gptr + G, N);

    // ---- layer 1: x@W1 -> gather -> BN params (linear bias cancels in BN) ----
    k_gemm1<<<(N + 7) / 8, 256>>>(x, W1, hw, N);
    k_gather<128><<<(N + 7) / 8, 256>>>(hw, dis, rowptr, esrc, agg, N);
    k_zero_stats<<<1, 128>>>(128);
    k_stats<<<1024, 128>>>(agg, N, 128);
    k_finalize_bn<<<1, 128>>>(gm1, be1, N, 128);

    // ---- layer 2 ----
    {
        dim3 grid(2, (N + 127) / 128);
        k_sgemm<true, false><<<grid, 256>>>(agg, W2, hw, N, 128, 256, scale, shift, nullptr);
    }
    k_gather<256><<<(N + 7) / 8, 256>>>(hw, dis, rowptr, esrc, agg, N);
    k_zero_stats<<<1, 256>>>(256);
    k_stats<<<1024, 256>>>(agg, N, 256);
    k_finalize_bn<<<1, 256>>>(gm2, be2, N, 256);

    // ---- layer 3 ----
    {
        dim3 grid(2, (N + 127) / 128);
        k_sgemm<true, false><<<grid, 256>>>(agg, W3, hw, N, 256, 256, scale, shift, nullptr);
    }
    k_gather<256><<<(N + 7) / 8, 256>>>(hw, dis, rowptr, esrc, agg, N);
    k_zero_stats<<<1, 256>>>(256);
    k_stats<<<1024, 256>>>(agg, N, 256);
    k_finalize_bn<<<1, 256>>>(gm3, be3, N, 256);

    // ---- pooling (BN3 + relu fused, segmented, no atomics) ----
    k_pool<<<G, 256>>>(agg, gptr, pm);

    // ---- head: pm @ Wp + bp -> d_out ----
    {
        dim3 grid(P / 128, (G + 127) / 128);
        k_sgemm<false, true><<<grid, 256>>>(pm, Wp, (float*)d_out, G, 256, P,
                                            nullptr, nullptr, bp);
    }
}